// round 16
// baseline (speedup 1.0000x reference)
#include <cuda_runtime.h>
#include <cuda_bf16.h>
#include <cstdint>

// L, R: [N, C, H, W] fp32 ; out: [N, C, D, H, W] fp32
// out[n,c,d,h,w] = (w >= d) ? L[n,c,h,w] - R[n,c,h,w-d] : 1.0f
//
// R16 experiment: TMA bulk stores (cp.async.bulk shared->global, 1KB linear
// bursts) instead of per-thread STG — removes L1tex store wavefronts from
// the write path. Closes the last untested mechanism.
static constexpr int Nn = 2;
static constexpr int Cc = 32;
static constexpr int Hh = 128;
static constexpr int Ww = 256;
static constexpr int Dd = 48;

static constexpr int W4  = Ww / 4;         // 64 float4 per row
static constexpr int NCH = Nn * Cc * Hh;   // 8192 rows
static constexpr int HW  = Hh * Ww;

static constexpr int RPB    = 2;           // rows per block
static constexpr int BLOCK  = RPB * W4;    // 128 threads
static constexpr int DC     = 4;           // disparities per chunk
static constexpr int NCHUNK = Dd / DC;     // 12
static constexpr int NCOPY  = DC * RPB;    // 8 bulk copies per chunk
static constexpr int ROWB   = Ww * 4;      // 1024 bytes per (row,d) burst

__global__ __launch_bounds__(BLOCK)
void cost_volume_kernel(const float* __restrict__ L,
                        const float* __restrict__ R,
                        float* __restrict__ out)
{
    // Double-buffered staging: [buf][dd][row][w4] float4 = 16 KB.
    __shared__ float4 buf[2][DC][RPB][W4];

    const int tid = threadIdx.x;
    const int w4  = tid & (W4 - 1);          // 0..63
    const int r   = tid >> 6;                // 0..1 row within block
    const int row = blockIdx.x * RPB + r;    // 0..8191
    const int w   = w4 * 4;

    const float4* __restrict__ rrow4 =
        reinterpret_cast<const float4*>(R + (size_t)row * Ww);

    // L operand: one LDG.128, reused for all 48 disparities.
    float4 lv = __ldg(reinterpret_cast<const float4*>(L + (size_t)row * Ww) + w4);

    // Copy-issuing thread's fixed (dd, row) assignment and dst base.
    const int cp_dd = tid & (DC - 1);        // 0..3
    const int cp_r  = tid >> 2;              // 0..1 (valid for tid < 8)
    const int cp_row = blockIdx.x * RPB + (cp_r & (RPB - 1));
    const int cp_h   = cp_row & (Hh - 1);
    const int cp_nc  = cp_row >> 7;

    #pragma unroll
    for (int ci = 0; ci < NCHUNK; ++ci) {
        const int c = ci * DC;
        const int b = ci & 1;

        // Gate buffer reuse: chunk ci reuses buffer of chunk ci-2; each
        // issuing thread allows <=1 pending bulk group, then block-sync.
        if (ci >= 2) {
            if (tid < NCOPY)
                asm volatile("cp.async.bulk.wait_group 1;" ::: "memory");
            __syncthreads();
        }

        // Window r[w-c-4 .. w-c+7]: 3 aligned float4 (L2-resident).
        // Clamped addresses give garbage masked to 1.0 by (w>=d).
        float win[12];
        #pragma unroll
        for (int j = 0; j < 3; ++j) {
            int idx = w4 - (c >> 2) - 1 + j;
            idx = idx < 0 ? 0 : idx;
            float4 v = __ldg(rrow4 + idx);
            win[4 * j + 0] = v.x;
            win[4 * j + 1] = v.y;
            win[4 * j + 2] = v.z;
            win[4 * j + 3] = v.w;
        }

        // r[w+k-d] (d=c+dd) = win[4 + k - dd]; compile-time indices.
        #pragma unroll
        for (int dd = 0; dd < DC; ++dd) {
            const int d = c + dd;
            float4 o;
            o.x = (w + 0 >= d) ? (lv.x - win[4 + 0 - dd]) : 1.0f;
            o.y = (w + 1 >= d) ? (lv.y - win[5 - dd])     : 1.0f;
            o.z = (w + 2 >= d) ? (lv.z - win[6 - dd])     : 1.0f;
            o.w = (w + 3 >= d) ? (lv.w - win[7 - dd])     : 1.0f;
            buf[b][dd][r][w4] = o;           // conflict-free STS.128
        }
        __syncthreads();

        // 8 threads each issue one 1KB bulk copy smem->gmem, then commit.
        if (tid < NCOPY) {
            asm volatile("fence.proxy.async.shared::cta;" ::: "memory");
            float* dst = out +
                ((size_t)(cp_nc * Dd + c + cp_dd) * Hh + cp_h) * (size_t)Ww;
            uint32_t src = (uint32_t)__cvta_generic_to_shared(
                &buf[b][cp_dd][cp_r][0]);
            asm volatile(
                "cp.async.bulk.global.shared::cta.bulk_group [%0], [%1], %2;"
                :: "l"(dst), "r"(src), "r"(ROWB) : "memory");
            asm volatile("cp.async.bulk.commit_group;" ::: "memory");
        }
    }

    // Drain all pending bulk groups before exit.
    if (tid < NCOPY)
        asm volatile("cp.async.bulk.wait_group 0;" ::: "memory");
}

extern "C" void kernel_launch(void* const* d_in, const int* in_sizes, int n_in,
                              void* d_out, int out_size)
{
    const float* L = (const float*)d_in[0];
    const float* R = (const float*)d_in[1];
    float* out = (float*)d_out;

    const int grid = NCH / RPB;              // 4096 blocks, exact
    cost_volume_kernel<<<grid, BLOCK>>>(L, R, out);
}

// round 17
// speedup vs baseline: 1.1423x; 1.1423x over previous
#include <cuda_runtime.h>
#include <cuda_bf16.h>

// L, R: [N, C, H, W] fp32 ; out: [N, C, D, H, W] fp32
// out[n,c,d,h,w] = (w >= d) ? L[n,c,h,w] - R[n,c,h,w-d] : 1.0f
//
// FINAL kernel — HBM-write-roofline bound (~6.7 TB/s effective write stream,
// ~83% of pin spec; best of 16 measured variants). Design:
//  - one thread per (row, w4) float4 column; L loaded once, reused 48x
//  - R gathered from L2 via register windows (DCHUNK=24, regs=37, no spill)
//  - output written as evict-first streaming STG.128 (__stcs) — the single
//    biggest win of the series (-10%): zero-reuse stream must not pollute L2
//  - BLOCK=128 / grid=4096 for finest CTA scheduling granularity
static constexpr int Nn = 2;
static constexpr int Cc = 32;
static constexpr int Hh = 128;
static constexpr int Ww = 256;
static constexpr int Dd = 48;

static constexpr int W4   = Ww / 4;        // 64 float4 per row
static constexpr int NCH  = Nn * Cc * Hh;  // 8192 rows
static constexpr int HW   = Hh * Ww;
static constexpr int HW4  = HW / 4;        // float4 stride between d planes

static constexpr int BLOCK = 128;

static constexpr int DCHUNK = 24;              // disparities per register window
static constexpr int WINF4  = DCHUNK / 4 + 2;  // 8 float4 = 32 floats

__global__ __launch_bounds__(BLOCK)
void cost_volume_kernel(const float* __restrict__ L,
                        const float* __restrict__ R,
                        float* __restrict__ out)
{
    int tid = blockIdx.x * BLOCK + threadIdx.x; // exact grid: NCH*W4 threads
    int w4  = tid & (W4 - 1);                   // 0..63
    int row = tid >> 6;                         // 0..8191
    int h   = row & (Hh - 1);
    int nc  = row >> 7;

    int w = w4 * 4;

    const float4* __restrict__ rrow4 =
        reinterpret_cast<const float4*>(R + (size_t)row * Ww);

    // L operand: one LDG.128, reused for all 48 disparities.
    float4 lv = __ldg(reinterpret_cast<const float4*>(L + (size_t)row * Ww) + w4);

    float4* outp = reinterpret_cast<float4*>(
        out + ((size_t)(nc * Dd) * Hh + h) * (size_t)Ww + w);

    #pragma unroll
    for (int c = 0; c < Dd; c += DCHUNK) {
        // Register window over r[w-c-(DCHUNK-4) .. w-c+7] : WINF4 aligned
        // float4 loads (L2-resident). Addresses clamped to row start; clamped
        // garbage is masked to 1.0 by the (w>=d) predicate.
        float win[4 * WINF4];
        #pragma unroll
        for (int j = 0; j < WINF4; ++j) {
            int idx = w4 - (c >> 2) - (WINF4 - 2) + j;
            idx = idx < 0 ? 0 : idx;
            float4 v = __ldg(rrow4 + idx);
            win[4 * j + 0] = v.x;
            win[4 * j + 1] = v.y;
            win[4 * j + 2] = v.z;
            win[4 * j + 3] = v.w;
        }

        // Element r[w+k-d] (d = c+dd) lives at win[BASE + k - dd]; indices
        // are compile-time constants after unrolling -> window stays in regs.
        constexpr int BASE = 4 * (WINF4 - 2);

        #pragma unroll
        for (int dd = 0; dd < DCHUNK; ++dd) {
            const int d = c + dd;
            float4 o;
            o.x = (w + 0 >= d) ? (lv.x - win[BASE + 0 - dd]) : 1.0f;
            o.y = (w + 1 >= d) ? (lv.y - win[BASE + 1 - dd]) : 1.0f;
            o.z = (w + 2 >= d) ? (lv.z - win[BASE + 2 - dd]) : 1.0f;
            o.w = (w + 3 >= d) ? (lv.w - win[BASE + 3 - dd]) : 1.0f;
            // Streaming store: evict-first in L2 (zero-reuse output stream).
            __stcs(outp + (size_t)d * HW4, o);
        }
    }
}

extern "C" void kernel_launch(void* const* d_in, const int* in_sizes, int n_in,
                              void* d_out, int out_size)
{
    const float* L = (const float*)d_in[0];
    const float* R = (const float*)d_in[1];
    float* out = (float*)d_out;

    const int total_threads = NCH * W4;       // 524,288
    const int grid  = total_threads / BLOCK;  // 4096
    cost_volume_kernel<<<grid, BLOCK>>>(L, R, out);
}